// round 17
// baseline (speedup 1.0000x reference)
#include <cuda_runtime.h>
#include <math_constants.h>

// Problem shape (fixed by the benchmark)
#define BB   16
#define KC   5
#define NP   4096
#define DD   1024
#define KNN  9

#define BLK_X 32               // sims blocks per batch (512 total, one wave @4/SM)
#define RPG   2                // rows per unit
#define UPW   8                // units per warp
#define ROWS_PER_BLK 128
#define NCAND (BLK_X * KNN)    // 288 candidates per (b,k)
#define QD    4                // D-quarters in the gather kernel

// -------- scratch (no device allocation allowed -> __device__ globals) ------
__device__ float2   g_cand[BB * KC * NCAND];  // (val, idx-as-float-bits) 184 KB
__device__ float    g_invnorm[BB * NP];       // 1/||patch||             256 KB
__device__ int      g_top[BB * KC * KNN];     // merged winning indices
__device__ float    g_wsc[BB * KC * KNN];     // invnorm/9 of winners
__device__ unsigned g_count[BB];              // producer arrivals (0-init; reset in-kernel)

// -------- packed f32x2 helpers (accumulators 64-bit; patch loads stay float4)
typedef unsigned long long u64;
__device__ __forceinline__ u64 pk2(float lo, float hi) {
    u64 r;
    asm("mov.b64 %0, {%1, %2};" : "=l"(r) : "f"(lo), "f"(hi));
    return r;
}
__device__ __forceinline__ void fma2(u64& d, u64 a, u64 b) {
    asm("fma.rn.f32x2 %0, %1, %2, %0;" : "+l"(d) : "l"(a), "l"(b));
}
__device__ __forceinline__ float upk_sum(u64 p) {
    float lo, hi;
    asm("mov.b64 {%0, %1}, %2;" : "=f"(lo), "=f"(hi) : "l"(p));
    return lo + hi;
}

// ============================================================================
// Merge tail, __noinline__ so its registers cannot contaminate the streaming
// mainloop's allocation (R9 failure mode; R13 proved noinline keeps regs=64).
// Runs in the LAST-arriving sims block of each batch: warps 0-4 merge the 288
// candidates of cue k -> global top-9 -> g_top/g_wsc.
// ============================================================================
static __device__ __noinline__ void merge_batch(int b) {
    const int warp = threadIdx.x >> 5;
    const int lane = threadIdx.x & 31;
    if (warp >= KC) return;
    const int bk = b * KC + warp;

    const float2* cand = g_cand + (size_t)bk * NCAND;
    // lane holds slots lane + s*32, s = 0..8 (288 candidates, register resident)
    float v[9]; int x[9];
    #pragma unroll
    for (int s = 0; s < 9; s++) {
        const float2 c = cand[lane + s * 32];
        v[s] = c.x; x[s] = __float_as_int(c.y);
    }
    for (int it = 0; it < KNN; it++) {
        float bv = -CUDART_INF_F; int bi = NP; int bs = 0;
        #pragma unroll
        for (int s = 0; s < 9; s++)
            if (v[s] > bv || (v[s] == bv && x[s] < bi)) { bv = v[s]; bi = x[s]; bs = s; }
        int blane = lane;
        #pragma unroll
        for (int o = 16; o; o >>= 1) {
            const float ov = __shfl_xor_sync(0xffffffffu, bv, o);
            const int   oi = __shfl_xor_sync(0xffffffffu, bi, o);
            const int   os = __shfl_xor_sync(0xffffffffu, bs, o);
            const int   ol = __shfl_xor_sync(0xffffffffu, blane, o);
            if (ov > bv || (ov == bv && oi < bi)) { bv = ov; bi = oi; bs = os; blane = ol; }
        }
        if (lane == blane) v[bs] = -CUDART_INF_F;            // mask winner
        if (lane == 0) {
            g_top[bk * KNN + it] = bi;
            g_wsc[bk * KNN + it] =
                g_invnorm[(size_t)b * NP + bi] * (1.0f / (float)KNN);
        }
    }
}

// ============================================================================
// Kernel 1: one pass over patches (268 MB -> memory bound) + first-level
// top-9 per 128-row partition; the last-arriving block per batch also merges
// (threadfence reduction, zero spinning). Cue used RAW (positive row-scalar
// -> identical top-9 set; output only involves normalized patches).
// ============================================================================
__global__ void __launch_bounds__(256, 4) sims_kernel(const float* __restrict__ patches,
                                                      const float* __restrict__ cue) {
    const int b = blockIdx.y;
    const int bx = blockIdx.x;

    __shared__ ulonglong2 s_cue[KC * DD / 4];    // 20 KB raw cue as (f32,f32) pairs
    __shared__ float      s_s[KC][ROWS_PER_BLK]; // 2.5 KB block-local cosines
    __shared__ unsigned   s_arr;
    {
        const float4* src = (const float4*)(cue + (size_t)b * KC * DD);
        float4* dst = (float4*)s_cue;            // same 16B layout; lo word = .x
        for (int i = threadIdx.x; i < KC * DD / 4; i += 256) dst[i] = src[i];
    }
    __syncthreads();

    const int warp = threadIdx.x >> 5;
    const int lane = threadIdx.x & 31;
    const float4* pbase = (const float4*)(patches + (size_t)b * NP * DD);
    const int u0 = bx * (ROWS_PER_BLK / RPG);    // first unit of this block

    const float4* p = pbase + (size_t)(u0 + warp) * RPG * (DD / 4);
    float4 v[RPG], vn[RPG];
    #pragma unroll
    for (int rr = 0; rr < RPG; rr++)
        v[rr] = __ldcs(&p[lane + rr * (DD / 4)]);

    for (int m = 0; m < UPW; m++) {
        const bool has_next = (m < UPW - 1);
        const float4* pn = p + 8 * RPG * (DD / 4);    // next unit (stride 8)

        u64 acc[RPG][6];                              // packed (even,odd) sums
        #pragma unroll
        for (int rr = 0; rr < RPG; rr++)
            #pragma unroll
            for (int i = 0; i < 6; i++) acc[rr][i] = 0ull;

        #pragma unroll
        for (int j = 0; j < 8; j++) {
            // depth-1 prefetch: next chunk of this unit, or next unit's first
            if (j < 7) {
                const int offn = lane + (j + 1) * 32;
                #pragma unroll
                for (int rr = 0; rr < RPG; rr++)
                    vn[rr] = __ldcs(&p[offn + rr * (DD / 4)]);
            } else if (has_next) {
                #pragma unroll
                for (int rr = 0; rr < RPG; rr++)
                    vn[rr] = __ldcs(&pn[lane + rr * (DD / 4)]);
            }

            const int off = lane + j * 32;            // 256 16B-chunks per row
            u64 pv01[RPG], pv23[RPG];
            #pragma unroll
            for (int rr = 0; rr < RPG; rr++) {
                pv01[rr] = pk2(v[rr].x, v[rr].y);
                pv23[rr] = pk2(v[rr].z, v[rr].w);
                fma2(acc[rr][5], pv01[rr], pv01[rr]); // self-dot
                fma2(acc[rr][5], pv23[rr], pv23[rr]);
            }
            #pragma unroll
            for (int k = 0; k < KC; k++) {
                const ulonglong2 c2 = s_cue[k * (DD / 4) + off]; // pre-paired
                #pragma unroll
                for (int rr = 0; rr < RPG; rr++) {
                    fma2(acc[rr][k], pv01[rr], c2.x);
                    fma2(acc[rr][k], pv23[rr], c2.y);
                }
            }
            #pragma unroll
            for (int rr = 0; rr < RPG; rr++) v[rr] = vn[rr];
        }

        // epilogue: collapse packed pairs, butterfly -> sums in ALL lanes
        const int lrow0 = (warp + m * 8) * RPG;
        #pragma unroll
        for (int rr = 0; rr < RPG; rr++) {
            float s[6];
            #pragma unroll
            for (int i = 0; i < 6; i++) s[i] = upk_sum(acc[rr][i]);
            #pragma unroll
            for (int i = 0; i < 6; i++)
                #pragma unroll
                for (int o = 16; o; o >>= 1)
                    s[i] += __shfl_xor_sync(0xffffffffu, s[i], o);
            const float inv = rsqrtf(fmaxf(s[5], 1e-24f));
            float val = s[0];
            if (lane == 1) val = s[1];
            if (lane == 2) val = s[2];
            if (lane == 3) val = s[3];
            if (lane == 4) val = s[4];
            if (lane < 5)
                s_s[lane][lrow0 + rr] = val * inv;
            else if (lane == 5)
                g_invnorm[(size_t)b * NP + bx * ROWS_PER_BLK + lrow0 + rr] = inv;
        }

        if (has_next) p = pn;
    }
    __syncthreads();

    // Block-local top-9 per cue: warp k selects from s_s[k][0..128).
    if (warp < KC) {
        const int k = warp;
        float v4[4];
        const int base = lane * 4;
        #pragma unroll
        for (int i = 0; i < 4; i++) v4[i] = s_s[k][base + i];

        float2* cand = g_cand + ((size_t)(b * KC + k) * BLK_X + bx) * KNN;
        for (int it = 0; it < KNN; it++) {
            float bv = -CUDART_INF_F; int bi = ROWS_PER_BLK;
            #pragma unroll
            for (int i = 0; i < 4; i++)
                if (v4[i] > bv) { bv = v4[i]; bi = base + i; }   // lowest idx on tie
            #pragma unroll
            for (int o = 16; o; o >>= 1) {
                const float ov = __shfl_xor_sync(0xffffffffu, bv, o);
                const int   oi = __shfl_xor_sync(0xffffffffu, bi, o);
                if (ov > bv || (ov == bv && oi < bi)) { bv = ov; bi = oi; }
            }
            if ((bi >> 2) == lane) v4[bi & 3] = -CUDART_INF_F;   // mask winner
            if (lane == 0)
                cand[it] = make_float2(bv, __int_as_float(bx * ROWS_PER_BLK + bi));
        }
    }

    // threadfence reduction: last-arriving block of this batch merges.
    __syncthreads();
    __threadfence();                     // release cand/invnorm writes
    if (threadIdx.x == 0) s_arr = atomicAdd(&g_count[b], 1u);
    __syncthreads();
    if (s_arr == BLK_X - 1) {
        if (threadIdx.x == 0) g_count[b] = 0u;   // reset for graph replay
        __threadfence();                 // acquire all blocks' writes
        merge_batch(b);
    }
}

// ============================================================================
// Kernel 2: pure quarter-gather, no merge, no waiting. grid (QD, 80).
// Reads the merged g_top/g_wsc, gathers 9 quarter-rows, stores.
// ============================================================================
__global__ void __launch_bounds__(256) gather_kernel(const float* __restrict__ patches,
                                                     float* __restrict__ out) {
    const int q  = blockIdx.x;          // 0..3 D-quarter
    const int bk = blockIdx.y;          // 0..79
    const int b = bk / KC;
    const int tid = threadIdx.x;

    __shared__ int    s_top[KNN];
    __shared__ float  s_sc[KNN];
    __shared__ float4 s_part[3][DD / 4 / QD];   // 3 KB partials (groups 1..3)

    if (tid < KNN) {
        s_top[tid] = g_top[bk * KNN + tid];
        s_sc[tid]  = g_wsc[bk * KNN + tid];
    }
    __syncthreads();

    // Gather this block's quarter: 64 float4 columns. Group g = tid>>6 does
    // rows g, g+4 (+ row 8 for g==0); combine through smem.
    const int grp = tid >> 6;                    // 0..3
    const int cc  = tid & 63;                    // column within quarter
    const int col = q * (DD / 4 / QD) + cc;      // global float4 column

    float4 acc = make_float4(0.f, 0.f, 0.f, 0.f);
    #pragma unroll
    for (int s = 0; s < 2; s++) {
        const int i = grp + s * 4;               // rows 0..7 across groups
        const float4 v = ((const float4*)(patches + ((size_t)b * NP + s_top[i]) * DD))[col];
        const float sc = s_sc[i];
        acc.x = fmaf(v.x, sc, acc.x);
        acc.y = fmaf(v.y, sc, acc.y);
        acc.z = fmaf(v.z, sc, acc.z);
        acc.w = fmaf(v.w, sc, acc.w);
    }
    if (grp == 0) {                              // row 8
        const float4 v = ((const float4*)(patches + ((size_t)b * NP + s_top[8]) * DD))[col];
        const float sc = s_sc[8];
        acc.x = fmaf(v.x, sc, acc.x);
        acc.y = fmaf(v.y, sc, acc.y);
        acc.z = fmaf(v.z, sc, acc.z);
        acc.w = fmaf(v.w, sc, acc.w);
    }

    if (grp != 0) s_part[grp - 1][cc] = acc;
    __syncthreads();

    if (grp == 0) {
        #pragma unroll
        for (int g2 = 0; g2 < 3; g2++) {
            const float4 pz = s_part[g2][cc];
            acc.x += pz.x; acc.y += pz.y; acc.z += pz.z; acc.w += pz.w;
        }
        ((float4*)out)[(size_t)bk * (DD / 4) + col] = acc;
    }
}

// ============================================================================
extern "C" void kernel_launch(void* const* d_in, const int* in_sizes, int n_in,
                              void* d_out, int out_size) {
    const float* cue     = (const float*)d_in[0];
    const float* patches = (const float*)d_in[1];
    // defensive: identify by element count (cue = 81920, patches = 67108864)
    if (n_in >= 2 && in_sizes[0] > in_sizes[1]) {
        cue     = (const float*)d_in[1];
        patches = (const float*)d_in[0];
    }

    dim3 g1(BLK_X, BB);
    sims_kernel<<<g1, 256>>>(patches, cue);

    dim3 g2(QD, BB * KC);
    gather_kernel<<<g2, 256>>>(patches, (float*)d_out);
}